// round 1
// baseline (speedup 1.0000x reference)
#include <cuda_runtime.h>

// Problem constants (fixed by setup_inputs in the reference)
#define T_TRIG 48
#define S_SPAN 128
#define NNODE  (T_TRIG * S_SPAN)     // 6144
#define DIM    128                   // in_dim == heads*head_dim == 128
#define NHEADS 4
#define HDIM   32
#define DEG    (S_SPAN + T_TRIG - 1) // 175

// Scratch (device globals; no runtime allocation allowed)
__device__ float g_h  [NNODE * DIM];     // node features after linear, current layer
__device__ float g_A  [NNODE * NHEADS];  // a_src per node/head
__device__ float g_B  [NNODE * NHEADS];  // a_dst per node/head
__device__ float g_m  [NNODE * NHEADS];  // softmax max per dst/head
__device__ float g_rd [NNODE * NHEADS];  // 1/denom per dst/head
__device__ float g_tmp[NNODE * DIM];     // row-aggregation partial
__device__ float g_x1 [NNODE * DIM];     // layer-1 output

// ---------------------------------------------------------------------------
// K1: h = x @ W  (N x 128 @ 128 x 128), fused a_src/a_dst head dot-products.
// Block: 256 threads, 16 rows of x per block. grid = N/16 = 384.
// Thread layout: col = tid & 127, row-group rg = tid >> 7 (8 rows each).
// ---------------------------------------------------------------------------
__global__ void k_gemm_attn(const float* __restrict__ x,
                            const float* __restrict__ W,
                            const float* __restrict__ att_src,
                            const float* __restrict__ att_dst)
{
    __shared__ float xs[16][128];
    const int tid  = threadIdx.x;
    const int row0 = blockIdx.x * 16;

    for (int i = tid; i < 16 * 128; i += 256)
        xs[i >> 7][i & 127] = x[row0 * 128 + i];
    __syncthreads();

    const int col = tid & 127;
    const int rg  = tid >> 7;   // 0 or 1

    float acc[8];
#pragma unroll
    for (int r = 0; r < 8; r++) acc[r] = 0.f;

#pragma unroll 4
    for (int k = 0; k < 128; k++) {
        const float w = W[k * 128 + col];
#pragma unroll
        for (int r = 0; r < 8; r++)
            acc[r] = fmaf(xs[rg * 8 + r][k], w, acc[r]);
    }

#pragma unroll
    for (int r = 0; r < 8; r++)
        g_h[(row0 + rg * 8 + r) * 128 + col] = acc[r];

    // a_src / a_dst: warp w covers head (w & 3), lane = dim within head
    const int lane = tid & 31;
    const int head = (tid >> 5) & 3;
    const float as = att_src[head * 32 + lane];
    const float ad = att_dst[head * 32 + lane];

#pragma unroll
    for (int r = 0; r < 8; r++) {
        float ps = acc[r] * as;
        float pd = acc[r] * ad;
#pragma unroll
        for (int o = 16; o; o >>= 1) {
            ps += __shfl_xor_sync(0xffffffffu, ps, o);
            pd += __shfl_xor_sync(0xffffffffu, pd, o);
        }
        if (lane == 0) {
            const int n = row0 + rg * 8 + r;
            g_A[n * 4 + head] = ps;
            g_B[n * 4 + head] = pd;
        }
    }
}

// ---------------------------------------------------------------------------
// K2: per (dst node, head): softmax max + 1/denom over the 175 structured
// edges. One warp per (node, head). grid = N*4/8 blocks of 256 threads.
// ---------------------------------------------------------------------------
__global__ void k_stats()
{
    const int gw   = (blockIdx.x * blockDim.x + threadIdx.x) >> 5; // 0..24575
    const int lane = threadIdx.x & 31;
    const int n    = gw >> 2;
    const int head = gw & 3;
    const int r    = n >> 7;       // S_SPAN == 128
    const int c    = n & 127;

    const float b = g_B[n * 4 + head];

    float vals[6];
    int   cnt = 0;
    float mx  = -1e30f;

    for (int e = lane; e < DEG; e += 32) {
        int src;
        if (e < S_SPAN) {
            src = r * S_SPAN + e;                    // same-row (incl self)
        } else {
            int t = e - S_SPAN;                      // 0..T-2
            t += (t >= r);                           // skip own row
            src = t * S_SPAN + c;                    // same-column
        }
        float v = g_A[src * 4 + head] + b;
        v = v > 0.f ? v : 0.2f * v;                  // leaky_relu(0.2)
        vals[cnt++] = v;
        mx = fmaxf(mx, v);
    }
#pragma unroll
    for (int o = 16; o; o >>= 1)
        mx = fmaxf(mx, __shfl_xor_sync(0xffffffffu, mx, o));

    float s = 0.f;
    for (int i = 0; i < cnt; i++) s += __expf(vals[i] - mx);
#pragma unroll
    for (int o = 16; o; o >>= 1)
        s += __shfl_xor_sync(0xffffffffu, s, o);

    if (lane == 0) {
        g_m[gw]  = mx;
        g_rd[gw] = 1.f / s;
    }
}

// ---------------------------------------------------------------------------
// K3: row aggregation. Block = (row r, head, c-half). For the 64 dst columns
// in this half, accumulate sum over all 128 row-sources of alpha * h[src].
// Attention weights staged in padded shared (each exp computed once).
// grid = 48*4*2 = 384, block = 256 threads. Thread = (local dst cl, quarter q)
// computing 8 of the 32 head dims.
// ---------------------------------------------------------------------------
__global__ void k_row_agg()
{
    const int b    = blockIdx.x;
    const int r    = b >> 3;
    const int head = (b >> 1) & 3;
    const int ch   = b & 1;

    __shared__ float Hs[128 * 33];   // h[row srcs][32 head dims], padded
    __shared__ float ws[64 * 33];    // weights [local dst][32 src chunk], padded
    __shared__ float As[128];
    __shared__ float Bs[64], Ms[64], Rd[64];

    const int tid = threadIdx.x;

    for (int i = tid; i < 128 * 32; i += 256) {
        const int cp = i >> 5, d = i & 31;
        Hs[cp * 33 + d] = g_h[(r * 128 + cp) * 128 + head * 32 + d];
    }
    if (tid < 128) As[tid] = g_A[(r * 128 + tid) * 4 + head];
    if (tid < 64)        Bs[tid]       = g_B [(r * 128 + ch * 64 + tid)        * 4 + head];
    else if (tid < 128)  Ms[tid - 64]  = g_m [(r * 128 + ch * 64 + tid - 64)   * 4 + head];
    else if (tid < 192)  Rd[tid - 128] = g_rd[(r * 128 + ch * 64 + tid - 128)  * 4 + head];
    __syncthreads();

    const int cl = tid >> 2;   // local dst 0..63
    const int q  = tid & 3;    // dim quarter (8 dims)

    float acc[8];
#pragma unroll
    for (int d = 0; d < 8; d++) acc[d] = 0.f;

    for (int cc = 0; cc < 4; cc++) {       // 4 chunks of 32 sources
        // stage weights: 64 dst x 32 src = 2048 entries, 8 per thread
#pragma unroll
        for (int i = 0; i < 8; i++) {
            const int k  = tid + 256 * i;
            const int wc = k >> 5, j = k & 31;
            float v = As[cc * 32 + j] + Bs[wc];
            v = v > 0.f ? v : 0.2f * v;
            ws[wc * 33 + j] = __expf(v - Ms[wc]) * Rd[wc];
        }
        __syncthreads();

#pragma unroll
        for (int j = 0; j < 32; j++) {
            const float w = ws[cl * 33 + j];
            const float* hp = &Hs[(cc * 32 + j) * 33 + q * 8];
#pragma unroll
            for (int d = 0; d < 8; d++)
                acc[d] = fmaf(w, hp[d], acc[d]);
        }
        __syncthreads();
    }

    const int base = (r * 128 + ch * 64 + cl) * 128 + head * 32 + q * 8;
#pragma unroll
    for (int d = 0; d < 8; d++) g_tmp[base + d] = acc[d];
}

// ---------------------------------------------------------------------------
// K4: column aggregation (47 same-column srcs) + row partial + bias + ELU.
// Block per column c (128 blocks), 192 threads = (trig r, head).
// Shared h stored head-padded to avoid 4-way bank conflicts.
// ---------------------------------------------------------------------------
__global__ void k_col_agg(const float* __restrict__ bias, float* __restrict__ out)
{
    const int c   = blockIdx.x;
    const int tid = threadIdx.x;   // 192

    __shared__ float Hs[48 * 132];           // [t][head(33-padded)*32dims]
    __shared__ float As[192], Bs[192], Ms[192], Rd[192];

    for (int i = tid; i < 48 * 128; i += 192) {
        const int t = i >> 7, dim = i & 127;
        Hs[t * 132 + (dim >> 5) * 33 + (dim & 31)] = g_h[(t * 128 + c) * 128 + dim];
    }
    {
        const int t = tid >> 2, hh = tid & 3;
        const int idx = (t * 128 + c) * 4 + hh;
        As[tid] = g_A[idx];
        Bs[tid] = g_B[idx];
        Ms[tid] = g_m[idx];
        Rd[tid] = g_rd[idx];
    }
    __syncthreads();

    const int r    = tid >> 2;
    const int head = tid & 3;
    const float bb  = Bs[tid];
    const float mm  = Ms[tid];
    const float rdd = Rd[tid];

    float acc[32];
#pragma unroll
    for (int d = 0; d < 32; d++) acc[d] = 0.f;

    for (int t = 0; t < 48; t++) {
        if (t == r) continue;
        float v = As[t * 4 + head] + bb;
        v = v > 0.f ? v : 0.2f * v;
        const float w = __expf(v - mm) * rdd;
        const float* hp = &Hs[t * 132 + head * 33];
#pragma unroll
        for (int d = 0; d < 32; d++)
            acc[d] = fmaf(w, hp[d], acc[d]);
    }

    const int base = (r * 128 + c) * 128 + head * 32;
#pragma unroll
    for (int d = 0; d < 32; d++) {
        float v = g_tmp[base + d] + acc[d] + bias[head * 32 + d];
        out[base + d] = v > 0.f ? v : (__expf(v) - 1.f);   // ELU
    }
}

// ---------------------------------------------------------------------------
// Host side
// ---------------------------------------------------------------------------
static void run_layer(const float* x, const float* W, const float* asrc,
                      const float* adst, const float* bias, float* out)
{
    k_gemm_attn<<<NNODE / 16, 256>>>(x, W, asrc, adst);
    k_stats<<<(NNODE * NHEADS) / 8, 256>>>();
    k_row_agg<<<T_TRIG * NHEADS * 2, 256>>>();
    k_col_agg<<<S_SPAN, 192>>>(bias, out);
}

extern "C" void kernel_launch(void* const* d_in, const int* in_sizes, int n_in,
                              void* d_out, int out_size)
{
    const float* x0  = (const float*)d_in[0];  // pair_embeddings [1,48,128,128]
    const float* W1  = (const float*)d_in[1];
    const float* as1 = (const float*)d_in[2];
    const float* ad1 = (const float*)d_in[3];
    const float* b1  = (const float*)d_in[4];
    const float* W2  = (const float*)d_in[5];
    const float* as2 = (const float*)d_in[6];
    const float* ad2 = (const float*)d_in[7];
    const float* b2  = (const float*)d_in[8];

    float* x1 = nullptr;
    cudaGetSymbolAddress((void**)&x1, g_x1);

    run_layer(x0, W1, as1, ad1, b1, x1);
    run_layer(x1, W2, as2, ad2, b2, (float*)d_out);
}

// round 2
// speedup vs baseline: 1.5402x; 1.5402x over previous
#include <cuda_runtime.h>

#define T_TRIG 48
#define S_SPAN 128
#define NNODE  (T_TRIG * S_SPAN)     // 6144
#define DIM    128
#define NHEADS 4
#define HDIM   32
#define DEG    (S_SPAN + T_TRIG - 1) // 175

// Scratch (device globals; no runtime allocation allowed)
__device__ float g_h  [NNODE * DIM];
__device__ float g_A  [NNODE * NHEADS];
__device__ float g_B  [NNODE * NHEADS];
__device__ float g_m  [NNODE * NHEADS];
__device__ float g_rd [NNODE * NHEADS];
__device__ float g_tmp[NNODE * DIM];
__device__ float g_x1 [NNODE * DIM];

__device__ __forceinline__ float leaky02(float v) {
    return v > 0.f ? v : 0.2f * v;
}

// ---------------------------------------------------------------------------
// K1: h = x @ W  (N x 128 @ 128 x 128) + fused a_src/a_dst head dot products.
// grid = 384, block = 256. col = tid&127, rg = tid>>7 (8 rows each).
// xs reads vectorized as float4 (broadcast, conflict-free).
// ---------------------------------------------------------------------------
__global__ void __launch_bounds__(256)
k_gemm_attn(const float* __restrict__ x,
            const float* __restrict__ W,
            const float* __restrict__ att_src,
            const float* __restrict__ att_dst)
{
    __shared__ __align__(16) float xs[16 * 128];
    const int tid  = threadIdx.x;
    const int row0 = blockIdx.x * 16;

    {
        const float4* src4 = (const float4*)(x + row0 * 128);
        float4* dst4 = (float4*)xs;
#pragma unroll
        for (int i = 0; i < 2; i++)
            dst4[tid + 256 * i] = src4[tid + 256 * i];
    }
    __syncthreads();

    const int col = tid & 127;
    const int rg  = tid >> 7;
    const float* xb = &xs[rg * 8 * 128];

    float acc[8];
#pragma unroll
    for (int r = 0; r < 8; r++) acc[r] = 0.f;

#pragma unroll 4
    for (int k4 = 0; k4 < 32; k4++) {
        const float w0 = W[(k4 * 4 + 0) * 128 + col];
        const float w1 = W[(k4 * 4 + 1) * 128 + col];
        const float w2 = W[(k4 * 4 + 2) * 128 + col];
        const float w3 = W[(k4 * 4 + 3) * 128 + col];
#pragma unroll
        for (int r = 0; r < 8; r++) {
            const float4 xv = *(const float4*)&xb[r * 128 + k4 * 4];
            acc[r] = fmaf(xv.x, w0, acc[r]);
            acc[r] = fmaf(xv.y, w1, acc[r]);
            acc[r] = fmaf(xv.z, w2, acc[r]);
            acc[r] = fmaf(xv.w, w3, acc[r]);
        }
    }

#pragma unroll
    for (int r = 0; r < 8; r++)
        g_h[(row0 + rg * 8 + r) * 128 + col] = acc[r];

    // attention dot products: warp covers head (warp&3), lane = dim in head
    const int lane = tid & 31;
    const int head = (tid >> 5) & 3;
    const float as = att_src[head * 32 + lane];
    const float ad = att_dst[head * 32 + lane];

#pragma unroll
    for (int r = 0; r < 8; r++) {
        float ps = acc[r] * as;
        float pd = acc[r] * ad;
#pragma unroll
        for (int o = 16; o; o >>= 1) {
            ps += __shfl_xor_sync(0xffffffffu, ps, o);
            pd += __shfl_xor_sync(0xffffffffu, pd, o);
        }
        if (lane == 0) {
            const int n = row0 + rg * 8 + r;
            g_A[n * 4 + head] = ps;
            g_B[n * 4 + head] = pd;
        }
    }
}

// ---------------------------------------------------------------------------
// K2: row aggregation + fused softmax stats.
// Block = (row r, head, c-half). grid = 48*4*2 = 384, block = 256.
// Thread = (local dst cl = tid>>2, quarter q = tid&3) -> 8 head dims.
// Stats: 4 threads per dst each scan 32 row-A + 12 col-A values, xor-reduce.
// Shared padded to 36 floats so the 8-dim slices are two LDS.128 (broadcast).
// ---------------------------------------------------------------------------
__global__ void __launch_bounds__(256)
k_row_agg()
{
    const int b    = blockIdx.x;
    const int r    = b >> 3;
    const int head = (b >> 1) & 3;
    const int ch   = b & 1;

    __shared__ __align__(16) float Hs[128 * 36];  // h[src][32 dims], pad 36
    __shared__ __align__(16) float ws[64 * 36];   // weights [dst][src chunk]
    __shared__ float As[128];                     // row a_src
    __shared__ float CA[64 * 48];                 // column a_src per dst
    __shared__ float Bs[64], Ms[64], Rd[64];

    const int tid = threadIdx.x;

    // h slice: 128 src x 32 dims = 1024 float4
#pragma unroll
    for (int i = tid; i < 1024; i += 256) {
        const int cp = i >> 3, v = i & 7;
        const float4 val = *(const float4*)&g_h[(r * 128 + cp) * 128 + head * 32 + v * 4];
        *(float4*)&Hs[cp * 36 + v * 4] = val;
    }
    if (tid < 128) As[tid] = g_A[(r * 128 + tid) * 4 + head];
    else if (tid < 192) Bs[tid - 128] = g_B[(r * 128 + ch * 64 + (tid - 128)) * 4 + head];
    // column a_src: [dst cl][t]
    for (int i = tid; i < 64 * 48; i += 256) {
        const int cl = i / 48, t = i - cl * 48;
        CA[i] = g_A[(t * 128 + ch * 64 + cl) * 4 + head];
    }
    __syncthreads();

    const int cl = tid >> 2;
    const int q  = tid & 3;
    const int cg = ch * 64 + cl;
    const float B = Bs[cl];

    // --- softmax stats (max then denom), 4 threads per dst ---
    float mx = -1e30f;
#pragma unroll
    for (int j = 0; j < 32; j++)
        mx = fmaxf(mx, leaky02(As[q * 32 + j] + B));
#pragma unroll
    for (int t = q * 12; t < q * 12 + 12; t++) {
        if (t == r) continue;
        mx = fmaxf(mx, leaky02(CA[cl * 48 + t] + B));
    }
    mx = fmaxf(mx, __shfl_xor_sync(0xffffffffu, mx, 1));
    mx = fmaxf(mx, __shfl_xor_sync(0xffffffffu, mx, 2));

    float s = 0.f;
#pragma unroll
    for (int j = 0; j < 32; j++)
        s += __expf(leaky02(As[q * 32 + j] + B) - mx);
#pragma unroll
    for (int t = q * 12; t < q * 12 + 12; t++) {
        if (t == r) continue;
        s += __expf(leaky02(CA[cl * 48 + t] + B) - mx);
    }
    s += __shfl_xor_sync(0xffffffffu, s, 1);
    s += __shfl_xor_sync(0xffffffffu, s, 2);

    if (q == 0) {
        const float rd = 1.f / s;
        Ms[cl] = mx;
        Rd[cl] = rd;
        const int n = r * 128 + cg;
        g_m [n * 4 + head] = mx;
        g_rd[n * 4 + head] = rd;
    }
    __syncthreads();

    // --- weighted row aggregation ---
    float acc[8];
#pragma unroll
    for (int d = 0; d < 8; d++) acc[d] = 0.f;

    for (int cc = 0; cc < 4; cc++) {
        // stage 64 dst x 32 src weights, 8 per thread
#pragma unroll
        for (int i = 0; i < 8; i++) {
            const int k  = tid + 256 * i;
            const int wc = k >> 5, j = k & 31;
            const float v = leaky02(As[cc * 32 + j] + Bs[wc]);
            ws[wc * 36 + j] = __expf(v - Ms[wc]) * Rd[wc];
        }
        __syncthreads();

#pragma unroll
        for (int j = 0; j < 32; j++) {
            const float w = ws[cl * 36 + j];
            const float4 h0 = *(const float4*)&Hs[(cc * 32 + j) * 36 + q * 8];
            const float4 h1 = *(const float4*)&Hs[(cc * 32 + j) * 36 + q * 8 + 4];
            acc[0] = fmaf(w, h0.x, acc[0]);
            acc[1] = fmaf(w, h0.y, acc[1]);
            acc[2] = fmaf(w, h0.z, acc[2]);
            acc[3] = fmaf(w, h0.w, acc[3]);
            acc[4] = fmaf(w, h1.x, acc[4]);
            acc[5] = fmaf(w, h1.y, acc[5]);
            acc[6] = fmaf(w, h1.z, acc[6]);
            acc[7] = fmaf(w, h1.w, acc[7]);
        }
        __syncthreads();
    }

    const int base = (r * 128 + cg) * 128 + head * 32 + q * 8;
    float4 o0 = make_float4(acc[0], acc[1], acc[2], acc[3]);
    float4 o1 = make_float4(acc[4], acc[5], acc[6], acc[7]);
    *(float4*)&g_tmp[base]     = o0;
    *(float4*)&g_tmp[base + 4] = o1;
}

// ---------------------------------------------------------------------------
// K3: column aggregation + row partial + bias + ELU.
// grid = 128 cols * 2 r-halves = 256, block = 384 = (24 r, 4 head, 4 quarter).
// Head stride 36 / row stride 144 in shared: LDS.128-aligned and
// phase-conflict-free. Self-row weight predicated to zero (no divergence).
// ---------------------------------------------------------------------------
__global__ void __launch_bounds__(384)
k_col_agg(const float* __restrict__ bias, float* __restrict__ out)
{
    const int c  = blockIdx.x >> 1;
    const int rh = blockIdx.x & 1;
    const int tid = threadIdx.x;

    __shared__ __align__(16) float Hs[48 * 144];  // [t][head*36 + dim]
    __shared__ float Acol[48 * 4];                // [t][head]
    __shared__ float Bs[96], Ms[96], Rd[96];      // [r_local*4 + head]
    __shared__ float bsh[128];

    // h for all 48 column sources: 48*128 = 6144 floats = 1536 float4
#pragma unroll
    for (int i = tid; i < 1536; i += 384) {
        const int t = i >> 5, v = i & 31;       // v*4 = dim
        const float4 val = *(const float4*)&g_h[(t * 128 + c) * 128 + v * 4];
        const int dd = v * 4;
        *(float4*)&Hs[t * 144 + (dd >> 5) * 36 + (dd & 31)] = val;
    }
    if (tid < 192) {
        const int t = tid >> 2, hh = tid & 3;
        Acol[tid] = g_A[(t * 128 + c) * 4 + hh];
    } else if (tid < 288) {
        const int k = tid - 192;
        const int rg = rh * 24 + (k >> 2), hh = k & 3;
        const int idx = (rg * 128 + c) * 4 + hh;
        Bs[k] = g_B[idx];
        Ms[k] = g_m[idx];
        Rd[k] = g_rd[idx];
    }
    if (tid < 128) bsh[tid] = bias[tid];
    __syncthreads();

    const int rl   = tid >> 4;
    const int head = (tid >> 2) & 3;
    const int q    = tid & 3;
    const int rglob = rh * 24 + rl;

    const float B   = Bs[rl * 4 + head];
    const float mm  = Ms[rl * 4 + head];
    const float rdd = Rd[rl * 4 + head];

    float acc[8];
#pragma unroll
    for (int d = 0; d < 8; d++) acc[d] = 0.f;

#pragma unroll 4
    for (int t = 0; t < 48; t++) {
        const float v = leaky02(Acol[t * 4 + head] + B);
        float w = __expf(v - mm) * rdd;
        if (t == rglob) w = 0.f;
        const float4 h0 = *(const float4*)&Hs[t * 144 + head * 36 + q * 8];
        const float4 h1 = *(const float4*)&Hs[t * 144 + head * 36 + q * 8 + 4];
        acc[0] = fmaf(w, h0.x, acc[0]);
        acc[1] = fmaf(w, h0.y, acc[1]);
        acc[2] = fmaf(w, h0.z, acc[2]);
        acc[3] = fmaf(w, h0.w, acc[3]);
        acc[4] = fmaf(w, h1.x, acc[4]);
        acc[5] = fmaf(w, h1.y, acc[5]);
        acc[6] = fmaf(w, h1.z, acc[6]);
        acc[7] = fmaf(w, h1.w, acc[7]);
    }

    const int base = (rglob * 128 + c) * 128 + head * 32 + q * 8;
    const float4 t0 = *(const float4*)&g_tmp[base];
    const float4 t1 = *(const float4*)&g_tmp[base + 4];
    const int bb = head * 32 + q * 8;

    float vres[8];
    vres[0] = acc[0] + t0.x + bsh[bb + 0];
    vres[1] = acc[1] + t0.y + bsh[bb + 1];
    vres[2] = acc[2] + t0.z + bsh[bb + 2];
    vres[3] = acc[3] + t0.w + bsh[bb + 3];
    vres[4] = acc[4] + t1.x + bsh[bb + 4];
    vres[5] = acc[5] + t1.y + bsh[bb + 5];
    vres[6] = acc[6] + t1.z + bsh[bb + 6];
    vres[7] = acc[7] + t1.w + bsh[bb + 7];
#pragma unroll
    for (int d = 0; d < 8; d++)
        vres[d] = vres[d] > 0.f ? vres[d] : (__expf(vres[d]) - 1.f);

    *(float4*)&out[base]     = make_float4(vres[0], vres[1], vres[2], vres[3]);
    *(float4*)&out[base + 4] = make_float4(vres[4], vres[5], vres[6], vres[7]);
}

// ---------------------------------------------------------------------------
static void run_layer(const float* x, const float* W, const float* asrc,
                      const float* adst, const float* bias, float* out)
{
    k_gemm_attn<<<NNODE / 16, 256>>>(x, W, asrc, adst);
    k_row_agg<<<T_TRIG * NHEADS * 2, 256>>>();
    k_col_agg<<<S_SPAN * 2, 384>>>(bias, out);
}

extern "C" void kernel_launch(void* const* d_in, const int* in_sizes, int n_in,
                              void* d_out, int out_size)
{
    const float* x0  = (const float*)d_in[0];
    const float* W1  = (const float*)d_in[1];
    const float* as1 = (const float*)d_in[2];
    const float* ad1 = (const float*)d_in[3];
    const float* b1  = (const float*)d_in[4];
    const float* W2  = (const float*)d_in[5];
    const float* as2 = (const float*)d_in[6];
    const float* ad2 = (const float*)d_in[7];
    const float* b2  = (const float*)d_in[8];

    float* x1 = nullptr;
    cudaGetSymbolAddress((void**)&x1, g_x1);

    run_layer(x0, W1, as1, ad1, b1, x1);
    run_layer(x1, W2, as2, ad2, b2, (float*)d_out);
}